// round 1
// baseline (speedup 1.0000x reference)
#include <cuda_runtime.h>
#include <cstddef>
#include <cstdint>
#include <math.h>

// Problem dims (fixed by reference)
#define BB   2
#define TT   2048
#define HID  2048
#define KVD  1024
#define VOC  32000
#define MTOT (BB * TT)          // 4096 flattened rows for h/e/ctx

// Scratch (no allocation allowed -> __device__ globals)
__device__ float g_q[(size_t)MTOT * KVD];          // 16 MB
__device__ float g_k[(size_t)MTOT * KVD];          // 16 MB
__device__ float g_v[(size_t)MTOT * KVD];          // 16 MB
__device__ float g_ctx[(size_t)MTOT * KVD];        // 16 MB
__device__ float g_scores[(size_t)BB * TT * TT];   // 33.5 MB

// ---------------------------------------------------------------------------
// NT GEMM: C[M,N] = scale * A[M,K] @ B[N,K]^T (+ bias[n])
// Both A and B row-major with K contiguous. 128x128 tile, BK=8, 8x8/thread.
// All dims assumed multiples of tile sizes (true for this problem).
// CAUSAL: skip blocks entirely above the diagonal (used for scores).
// ---------------------------------------------------------------------------
template <bool CAUSAL>
__global__ void __launch_bounds__(256, 2)
gemm_nt_kernel(const float* __restrict__ A, const float* __restrict__ B,
               float* __restrict__ C, const float* __restrict__ bias,
               int M, int N, int K, float scale,
               size_t sA, size_t sB, size_t sC)
{
    const int bz = blockIdx.z;
    A += (size_t)bz * sA;
    B += (size_t)bz * sB;
    C += (size_t)bz * sC;

    const int m0 = blockIdx.y * 128;
    const int n0 = blockIdx.x * 128;
    if (CAUSAL && n0 > m0 + 127) return;   // entire block disallowed

    __shared__ float As[8][128];
    __shared__ float Bs[8][128];

    const int tid = threadIdx.x;
    const int tx = tid & 15;        // 0..15 -> n sub-tile
    const int ty = tid >> 4;        // 0..15 -> m sub-tile

    const int lr = tid >> 1;        // 0..127 row within tile for loads
    const int lc = (tid & 1) * 4;   // 0 or 4: k offset (float4)

    const float* Aptr = A + (size_t)(m0 + lr) * K + lc;
    const float* Bptr = B + (size_t)(n0 + lr) * K + lc;

    float acc[8][8];
#pragma unroll
    for (int i = 0; i < 8; i++)
#pragma unroll
        for (int j = 0; j < 8; j++) acc[i][j] = 0.f;

    for (int k0 = 0; k0 < K; k0 += 8) {
        float4 av = *reinterpret_cast<const float4*>(Aptr + k0);
        float4 bv = *reinterpret_cast<const float4*>(Bptr + k0);
        __syncthreads();
        As[lc + 0][lr] = av.x; As[lc + 1][lr] = av.y;
        As[lc + 2][lr] = av.z; As[lc + 3][lr] = av.w;
        Bs[lc + 0][lr] = bv.x; Bs[lc + 1][lr] = bv.y;
        Bs[lc + 2][lr] = bv.z; Bs[lc + 3][lr] = bv.w;
        __syncthreads();

#pragma unroll
        for (int kk = 0; kk < 8; kk++) {
            float a[8], b[8];
            float4 a0 = *reinterpret_cast<const float4*>(&As[kk][ty * 8]);
            float4 a1 = *reinterpret_cast<const float4*>(&As[kk][ty * 8 + 4]);
            float4 b0 = *reinterpret_cast<const float4*>(&Bs[kk][tx * 8]);
            float4 b1 = *reinterpret_cast<const float4*>(&Bs[kk][tx * 8 + 4]);
            a[0]=a0.x; a[1]=a0.y; a[2]=a0.z; a[3]=a0.w;
            a[4]=a1.x; a[5]=a1.y; a[6]=a1.z; a[7]=a1.w;
            b[0]=b0.x; b[1]=b0.y; b[2]=b0.z; b[3]=b0.w;
            b[4]=b1.x; b[5]=b1.y; b[6]=b1.z; b[7]=b1.w;
#pragma unroll
            for (int i = 0; i < 8; i++)
#pragma unroll
                for (int j = 0; j < 8; j++)
                    acc[i][j] = fmaf(a[i], b[j], acc[i][j]);
        }
    }

    // Epilogue
#pragma unroll
    for (int i = 0; i < 8; i++) {
        const int m = m0 + ty * 8 + i;
        float* Crow = C + (size_t)m * N + n0 + tx * 8;
        float4 o0, o1;
        if (bias) {
            const float* brow = bias + n0 + tx * 8;
            o0.x = acc[i][0] * scale + brow[0];
            o0.y = acc[i][1] * scale + brow[1];
            o0.z = acc[i][2] * scale + brow[2];
            o0.w = acc[i][3] * scale + brow[3];
            o1.x = acc[i][4] * scale + brow[4];
            o1.y = acc[i][5] * scale + brow[5];
            o1.z = acc[i][6] * scale + brow[6];
            o1.w = acc[i][7] * scale + brow[7];
        } else {
            o0.x = acc[i][0] * scale; o0.y = acc[i][1] * scale;
            o0.z = acc[i][2] * scale; o0.w = acc[i][3] * scale;
            o1.x = acc[i][4] * scale; o1.y = acc[i][5] * scale;
            o1.z = acc[i][6] * scale; o1.w = acc[i][7] * scale;
        }
        *reinterpret_cast<float4*>(Crow)     = o0;
        *reinterpret_cast<float4*>(Crow + 4) = o1;
    }
}

// ---------------------------------------------------------------------------
// NN GEMM: C[M,N] = A[M,K] @ B[K,N]   (ctx = attn @ V)
// A row-major K-contiguous, B row-major N-contiguous.
// causalClamp: attn[m,s]==0 for s>m, so k-loop only needs k < m0+128.
// ---------------------------------------------------------------------------
__global__ void __launch_bounds__(256, 2)
gemm_nn_kernel(const float* __restrict__ A, const float* __restrict__ B,
               float* __restrict__ C, int M, int N, int K,
               size_t sA, size_t sB, size_t sC, int causalClamp)
{
    const int bz = blockIdx.z;
    A += (size_t)bz * sA;
    B += (size_t)bz * sB;
    C += (size_t)bz * sC;

    const int m0 = blockIdx.y * 128;
    const int n0 = blockIdx.x * 128;

    __shared__ float As[8][128];
    __shared__ float Bs[8][128];

    const int tid = threadIdx.x;
    const int tx = tid & 15;
    const int ty = tid >> 4;

    // A-tile load (transpose): row m0+lrA, cols k0+lcA..+3
    const int lrA = tid >> 1;
    const int lcA = (tid & 1) * 4;
    // B-tile load (direct): row k0+lrB, cols n0+lcB..+3
    const int lrB = tid >> 5;          // 0..7
    const int lcB = (tid & 31) * 4;    // 0..124

    const float* Aptr = A + (size_t)(m0 + lrA) * K + lcA;

    float acc[8][8];
#pragma unroll
    for (int i = 0; i < 8; i++)
#pragma unroll
        for (int j = 0; j < 8; j++) acc[i][j] = 0.f;

    const int kEnd = causalClamp ? ((m0 + 128 < K) ? (m0 + 128) : K) : K;

    for (int k0 = 0; k0 < kEnd; k0 += 8) {
        float4 av = *reinterpret_cast<const float4*>(Aptr + k0);
        float4 bv = *reinterpret_cast<const float4*>(
            B + (size_t)(k0 + lrB) * N + n0 + lcB);
        __syncthreads();
        As[lcA + 0][lrA] = av.x; As[lcA + 1][lrA] = av.y;
        As[lcA + 2][lrA] = av.z; As[lcA + 3][lrA] = av.w;
        *reinterpret_cast<float4*>(&Bs[lrB][lcB]) = bv;
        __syncthreads();

#pragma unroll
        for (int kk = 0; kk < 8; kk++) {
            float a[8], b[8];
            float4 a0 = *reinterpret_cast<const float4*>(&As[kk][ty * 8]);
            float4 a1 = *reinterpret_cast<const float4*>(&As[kk][ty * 8 + 4]);
            float4 b0 = *reinterpret_cast<const float4*>(&Bs[kk][tx * 8]);
            float4 b1 = *reinterpret_cast<const float4*>(&Bs[kk][tx * 8 + 4]);
            a[0]=a0.x; a[1]=a0.y; a[2]=a0.z; a[3]=a0.w;
            a[4]=a1.x; a[5]=a1.y; a[6]=a1.z; a[7]=a1.w;
            b[0]=b0.x; b[1]=b0.y; b[2]=b0.z; b[3]=b0.w;
            b[4]=b1.x; b[5]=b1.y; b[6]=b1.z; b[7]=b1.w;
#pragma unroll
            for (int i = 0; i < 8; i++)
#pragma unroll
                for (int j = 0; j < 8; j++)
                    acc[i][j] = fmaf(a[i], b[j], acc[i][j]);
        }
    }

#pragma unroll
    for (int i = 0; i < 8; i++) {
        const int m = m0 + ty * 8 + i;
        float* Crow = C + (size_t)m * N + n0 + tx * 8;
        float4 o0, o1;
        o0.x = acc[i][0]; o0.y = acc[i][1]; o0.z = acc[i][2]; o0.w = acc[i][3];
        o1.x = acc[i][4]; o1.y = acc[i][5]; o1.z = acc[i][6]; o1.w = acc[i][7];
        *reinterpret_cast<float4*>(Crow)     = o0;
        *reinterpret_cast<float4*>(Crow + 4) = o1;
    }
}

// ---------------------------------------------------------------------------
// Masked causal softmax, in-place on scores[b,t,:].
// allowed(s) = (s <= t) && (mask[b,s] != 0). Disallowed entries -> 0.
// Fully-masked rows -> all zeros (matches reference nan_to_num semantics).
// ---------------------------------------------------------------------------
__global__ void softmax_kernel(float* __restrict__ scores,
                               const int* __restrict__ mask)
{
    const int t = blockIdx.x;
    const int b = blockIdx.y;
    float* row = scores + ((size_t)b * TT + t) * TT;
    const int* mrow = mask + b * TT;
    const int tid = threadIdx.x;          // 256 threads

    __shared__ float red[256];

    // Pass 1: max over allowed
    float mx = -INFINITY;
    for (int s = tid; s <= t; s += 256)
        if (mrow[s]) mx = fmaxf(mx, row[s]);
    red[tid] = mx;
    __syncthreads();
    for (int w = 128; w > 0; w >>= 1) {
        if (tid < w) red[tid] = fmaxf(red[tid], red[tid + w]);
        __syncthreads();
    }
    mx = red[0];
    __syncthreads();

    // Pass 2: exp & sum; write exp (or 0 for disallowed) in place over full row
    float sum = 0.f;
    for (int s = tid; s < TT; s += 256) {
        float val = 0.f;
        if (s <= t && mrow[s]) {
            val = expf(row[s] - mx);
            sum += val;
        }
        row[s] = val;
    }
    red[tid] = sum;
    __syncthreads();
    for (int w = 128; w > 0; w >>= 1) {
        if (tid < w) red[tid] += red[tid + w];
        __syncthreads();
    }
    sum = red[0];
    __syncthreads();

    const float inv = (sum > 0.f) ? 1.f / sum : 0.f;
    // Pass 3: normalize (only allowed region can be nonzero)
    for (int s = tid; s <= t; s += 256) row[s] *= inv;
}

// ---------------------------------------------------------------------------
// Launch
// ---------------------------------------------------------------------------
extern "C" void kernel_launch(void* const* d_in, const int* in_sizes, int n_in,
                              void* d_out, int out_size)
{
    const float* h    = (const float*)d_in[0];
    const float* e    = (const float*)d_in[1];
    const int*   mask = (const int*)  d_in[2];
    const float* Wq   = (const float*)d_in[3];
    const float* Wk   = (const float*)d_in[4];
    const float* Wv   = (const float*)d_in[5];
    const float* Wout = (const float*)d_in[6];
    const float* bout = (const float*)d_in[7];
    float* out = (float*)d_out;

    float *q, *k, *v, *ctx, *sc;
    cudaGetSymbolAddress((void**)&q,   g_q);
    cudaGetSymbolAddress((void**)&k,   g_k);
    cudaGetSymbolAddress((void**)&v,   g_v);
    cudaGetSymbolAddress((void**)&ctx, g_ctx);
    cudaGetSymbolAddress((void**)&sc,  g_scores);

    const float att_scale = 1.0f / 32.0f;   // KV^-0.5 = 1024^-0.5

    // 1) Q/K/V projections: [4096,2048] @ [1024,2048]^T
    {
        dim3 grid(KVD / 128, MTOT / 128, 1);
        gemm_nt_kernel<false><<<grid, 256>>>(h, Wq, q, nullptr,
                                             MTOT, KVD, HID, 1.f, 0, 0, 0);
        gemm_nt_kernel<false><<<grid, 256>>>(e, Wk, k, nullptr,
                                             MTOT, KVD, HID, 1.f, 0, 0, 0);
        gemm_nt_kernel<false><<<grid, 256>>>(e, Wv, v, nullptr,
                                             MTOT, KVD, HID, 1.f, 0, 0, 0);
    }

    // 2) scores[b] = scale * q[b] @ k[b]^T  (causal block-skip)
    {
        dim3 grid(TT / 128, TT / 128, BB);
        gemm_nt_kernel<true><<<grid, 256>>>(
            q, k, sc, nullptr, TT, TT, KVD, att_scale,
            (size_t)TT * KVD, (size_t)TT * KVD, (size_t)TT * TT);
    }

    // 3) masked causal softmax (in place)
    {
        dim3 grid(TT, BB);
        softmax_kernel<<<grid, 256>>>(sc, mask);
    }

    // 4) ctx[b] = attn[b] @ v[b]  (K-loop clamped by causality)
    {
        dim3 grid(KVD / 128, TT / 128, BB);
        gemm_nn_kernel<<<grid, 256>>>(
            sc, v, ctx, TT, KVD, TT,
            (size_t)TT * TT, (size_t)TT * KVD, (size_t)TT * KVD, 1);
    }

    // 5) out = ctx @ Wout^T + bout : [4096,1024] @ [32000,1024]^T
    {
        dim3 grid(VOC / 128, MTOT / 128, 1);
        gemm_nt_kernel<false><<<grid, 256>>>(ctx, Wout, out, bout,
                                             MTOT, VOC, KVD, 1.f, 0, 0, 0);
    }
}

// round 3
// speedup vs baseline: 2.5402x; 2.5402x over previous
#include <cuda_runtime.h>
#include <cstddef>
#include <cstdint>
#include <math.h>

// ---------------------------------------------------------------------------
// Problem dims
// ---------------------------------------------------------------------------
#define BBATCH 2
#define TT   2048
#define HID  2048
#define KVD  1024
#define VOC  32000
#define MTOT (BBATCH * TT)   // 4096

// ---------------------------------------------------------------------------
// Scratch (__device__ globals; no allocation allowed)
// ---------------------------------------------------------------------------
__device__ __align__(256) float g_q[(size_t)MTOT * KVD];
__device__ __align__(256) float g_k[(size_t)MTOT * KVD];
__device__ __align__(256) float g_v[(size_t)MTOT * KVD];
__device__ __align__(256) float g_ctx[(size_t)MTOT * KVD];
__device__ __align__(256) float g_scores[(size_t)BBATCH * TT * TT];

// ---------------------------------------------------------------------------
// Helpers
// ---------------------------------------------------------------------------
__device__ __forceinline__ uint32_t s2u(const void* p) {
    uint32_t a;
    asm("{ .reg .u64 t; cvta.to.shared.u64 t, %1; cvt.u32.u64 %0, t; }"
        : "=r"(a) : "l"(p));
    return a;
}

__device__ __forceinline__ void cpasync16(uint32_t dst, const void* src) {
    asm volatile("cp.async.cg.shared.global [%0], [%1], 16;"
                 :: "r"(dst), "l"(src));
}
#define CP_COMMIT() asm volatile("cp.async.commit_group;" ::: "memory")
#define CP_WAIT1()  asm volatile("cp.async.wait_group 1;"  ::: "memory")

__device__ __forceinline__ uint32_t f2tf(float f) {
    uint32_t u;
    asm("cvt.rna.tf32.f32 %0, %1;" : "=r"(u) : "f"(f));
    return u;
}

__device__ __forceinline__ void mma8(float* c, const uint32_t* a, const uint32_t* b) {
    asm volatile(
        "mma.sync.aligned.m16n8k8.row.col.f32.tf32.tf32.f32 "
        "{%0,%1,%2,%3}, {%4,%5,%6,%7}, {%8,%9}, {%0,%1,%2,%3};"
        : "+f"(c[0]), "+f"(c[1]), "+f"(c[2]), "+f"(c[3])
        : "r"(a[0]), "r"(a[1]), "r"(a[2]), "r"(a[3]),
          "r"(b[0]), "r"(b[1]));
}

// ---------------------------------------------------------------------------
// Tensor-core tf32 GEMMs.
// CTA tile 128x128, BK=32 fp32, 3-stage cp.async pipeline.
// 8 warps: warp (wid&3 -> m quarter of 32 rows, wid>>2 -> n half of 64 cols).
// Warp tile 32x64 = 2 m16-tiles x 8 n8-tiles, 4 k8-steps per BK.
// SMEM per stage: A 128x32 f32 (16KB, xor-swizzled) + B 16KB = 32KB; 3 stages.
// ---------------------------------------------------------------------------
#define STAGE_B   32768u
#define STAGE_F   8192
#define GEMM_SMEM (3 * 32768)

// --- NT: C[M,N] = scale * A[M,K] @ B[N,K]^T (+ bias). A,B row-major K-contig.
template <bool CAUSAL, bool HASBIAS>
__global__ void __launch_bounds__(256)
tc_nt_kernel(const float* __restrict__ A, const float* __restrict__ B,
             float* __restrict__ C, const float* __restrict__ bias,
             int M, int N, int K, float scale,
             size_t sA, size_t sB, size_t sC)
{
    extern __shared__ float sm[];
    A += (size_t)blockIdx.z * sA;
    B += (size_t)blockIdx.z * sB;
    C += (size_t)blockIdx.z * sC;
    const int m0 = blockIdx.x * 128;
    const int n0 = blockIdx.y * 128;
    if (CAUSAL && n0 > m0 + 127) return;

    const int tid  = threadIdx.x;
    const int lane = tid & 31;
    const int wid  = tid >> 5;
    const int wm   = (wid & 3) * 32;
    const int wn   = (wid >> 2) * 64;
    const uint32_t su = s2u(sm);

    // global->smem loader: each thread owns half a 128B row (4x16B) of A and B
    const int lrow = tid >> 1;
    const int kb   = (tid & 1) * 16;
    const float* Ag = A + (size_t)(m0 + lrow) * K + kb;
    const float* Bg = B + (size_t)(n0 + lrow) * K + kb;
    uint32_t aoff[4], boff[4];
#pragma unroll
    for (int i = 0; i < 4; i++) {
        int k = kb + i * 4;
        uint32_t o = (uint32_t)(lrow * 32 + (k ^ ((lrow & 7) * 4))) * 4;
        aoff[i] = o;
        boff[i] = o + 16384u;
    }

    const int nk = K / 32;

#pragma unroll
    for (int st = 0; st < 2; st++) {
#pragma unroll
        for (int i = 0; i < 4; i++) {
            cpasync16(su + (uint32_t)st * STAGE_B + aoff[i], Ag + st * 32 + i * 4);
            cpasync16(su + (uint32_t)st * STAGE_B + boff[i], Bg + st * 32 + i * 4);
        }
        CP_COMMIT();
    }

    float acc[2][8][4];
#pragma unroll
    for (int mt = 0; mt < 2; mt++)
#pragma unroll
        for (int nt = 0; nt < 8; nt++)
#pragma unroll
            for (int j = 0; j < 4; j++) acc[mt][nt][j] = 0.f;

    for (int c = 0; c < nk; c++) {
        CP_WAIT1();
        __syncthreads();

        const int p = c + 2;
        if (p < nk) {
            const uint32_t sb = (uint32_t)(p % 3) * STAGE_B;
#pragma unroll
            for (int i = 0; i < 4; i++) {
                cpasync16(su + sb + aoff[i], Ag + p * 32 + i * 4);
                cpasync16(su + sb + boff[i], Bg + p * 32 + i * 4);
            }
        }
        CP_COMMIT();

        const float* sA_ = sm + (c % 3) * STAGE_F;
        const float* sB_ = sA_ + 4096;

#pragma unroll
        for (int ks = 0; ks < 4; ks++) {
            const int kq = ks * 8 + (lane & 3);
            uint32_t bf[8][2];
#pragma unroll
            for (int nt = 0; nt < 8; nt++) {
                int n  = wn + nt * 8 + (lane >> 2);
                int sw = (n & 7) * 4;
                bf[nt][0] = f2tf(sB_[n * 32 + (kq ^ sw)]);
                bf[nt][1] = f2tf(sB_[n * 32 + ((kq + 4) ^ sw)]);
            }
#pragma unroll
            for (int mt = 0; mt < 2; mt++) {
                int m  = wm + mt * 16 + (lane >> 2);
                int sw = (m & 7) * 4;       // (m+8)&7 == m&7
                uint32_t af[4];
                af[0] = f2tf(sA_[m * 32 + (kq ^ sw)]);
                af[1] = f2tf(sA_[(m + 8) * 32 + (kq ^ sw)]);
                af[2] = f2tf(sA_[m * 32 + ((kq + 4) ^ sw)]);
                af[3] = f2tf(sA_[(m + 8) * 32 + ((kq + 4) ^ sw)]);
#pragma unroll
                for (int nt = 0; nt < 8; nt++)
                    mma8(acc[mt][nt], af, bf[nt]);
            }
        }
    }

    // Epilogue
#pragma unroll
    for (int mt = 0; mt < 2; mt++) {
        const int r0 = m0 + wm + mt * 16 + (lane >> 2);
#pragma unroll
        for (int nt = 0; nt < 8; nt++) {
            const int col = n0 + wn + nt * 8 + (lane & 3) * 2;
            float bx = 0.f, by = 0.f;
            if (HASBIAS) {
                float2 bv = *reinterpret_cast<const float2*>(bias + col);
                bx = bv.x; by = bv.y;
            }
            float2 v0 = make_float2(acc[mt][nt][0] * scale + bx,
                                    acc[mt][nt][1] * scale + by);
            float2 v1 = make_float2(acc[mt][nt][2] * scale + bx,
                                    acc[mt][nt][3] * scale + by);
            *reinterpret_cast<float2*>(C + (size_t)r0 * N + col)       = v0;
            *reinterpret_cast<float2*>(C + (size_t)(r0 + 8) * N + col) = v1;
        }
    }
}

// --- NN: C[M,N] = A[M,K] @ B[K,N]. A row-major K-contig, B row-major N-contig.
__global__ void __launch_bounds__(256)
tc_nn_kernel(const float* __restrict__ A, const float* __restrict__ B,
             float* __restrict__ C, int M, int N, int K,
             size_t sA, size_t sB, size_t sC, int causalClamp)
{
    extern __shared__ float sm[];
    A += (size_t)blockIdx.z * sA;
    B += (size_t)blockIdx.z * sB;
    C += (size_t)blockIdx.z * sC;
    const int m0 = blockIdx.x * 128;
    const int n0 = blockIdx.y * 128;

    const int tid  = threadIdx.x;
    const int lane = tid & 31;
    const int wid  = tid >> 5;
    const int wm   = (wid & 3) * 32;
    const int wn   = (wid >> 2) * 64;
    const uint32_t su = s2u(sm);

    // A loader (same as NT)
    const int lrow = tid >> 1;
    const int kb   = (tid & 1) * 16;
    const float* Ag = A + (size_t)(m0 + lrow) * K + kb;
    uint32_t aoff[4];
#pragma unroll
    for (int i = 0; i < 4; i++) {
        int k = kb + i * 4;
        aoff[i] = (uint32_t)(lrow * 32 + (k ^ ((lrow & 7) * 4))) * 4;
    }

    // B loader: tile is 32(k) x 128(n) fp32; thread owns 4x16B of a k-row
    const int krow = tid >> 3;
    const int seg  = tid & 7;
    const float* Bg = B + (size_t)krow * N + n0 + seg * 16;
    uint32_t b2off[4];
#pragma unroll
    for (int i = 0; i < 4; i++) {
        int n = seg * 16 + i * 4;
        b2off[i] = (uint32_t)(krow * 128 + (n ^ ((krow & 3) * 8))) * 4 + 16384u;
    }

    int kEnd = causalClamp ? (m0 + 128 < K ? m0 + 128 : K) : K;
    const int nk = kEnd / 32;

#pragma unroll
    for (int st = 0; st < 2; st++) {
#pragma unroll
        for (int i = 0; i < 4; i++) {
            cpasync16(su + (uint32_t)st * STAGE_B + aoff[i],  Ag + st * 32 + i * 4);
            cpasync16(su + (uint32_t)st * STAGE_B + b2off[i], Bg + (size_t)st * 32 * N + i * 4);
        }
        CP_COMMIT();
    }

    float acc[2][8][4];
#pragma unroll
    for (int mt = 0; mt < 2; mt++)
#pragma unroll
        for (int nt = 0; nt < 8; nt++)
#pragma unroll
            for (int j = 0; j < 4; j++) acc[mt][nt][j] = 0.f;

    for (int c = 0; c < nk; c++) {
        CP_WAIT1();
        __syncthreads();

        const int p = c + 2;
        if (p < nk) {
            const uint32_t sb = (uint32_t)(p % 3) * STAGE_B;
#pragma unroll
            for (int i = 0; i < 4; i++) {
                cpasync16(su + sb + aoff[i],  Ag + p * 32 + i * 4);
                cpasync16(su + sb + b2off[i], Bg + (size_t)p * 32 * N + i * 4);
            }
        }
        CP_COMMIT();

        const float* sA_ = sm + (c % 3) * STAGE_F;
        const float* sB_ = sA_ + 4096;

#pragma unroll
        for (int ks = 0; ks < 4; ks++) {
            const int kq = ks * 8 + (lane & 3);
            const int swb = (kq & 3) * 8;   // (kq+4)&3 == kq&3
            uint32_t bf[8][2];
#pragma unroll
            for (int nt = 0; nt < 8; nt++) {
                int n = wn + nt * 8 + (lane >> 2);
                bf[nt][0] = f2tf(sB_[kq * 128 + (n ^ swb)]);
                bf[nt][1] = f2tf(sB_[(kq + 4) * 128 + (n ^ swb)]);
            }
#pragma unroll
            for (int mt = 0; mt < 2; mt++) {
                int m  = wm + mt * 16 + (lane >> 2);
                int sw = (m & 7) * 4;
                uint32_t af[4];
                af[0] = f2tf(sA_[m * 32 + (kq ^ sw)]);
                af[1] = f2tf(sA_[(m + 8) * 32 + (kq ^ sw)]);
                af[2] = f2tf(sA_[m * 32 + ((kq + 4) ^ sw)]);
                af[3] = f2tf(sA_[(m + 8) * 32 + ((kq + 4) ^ sw)]);
#pragma unroll
                for (int nt = 0; nt < 8; nt++)
                    mma8(acc[mt][nt], af, bf[nt]);
            }
        }
    }

#pragma unroll
    for (int mt = 0; mt < 2; mt++) {
        const int r0 = m0 + wm + mt * 16 + (lane >> 2);
#pragma unroll
        for (int nt = 0; nt < 8; nt++) {
            const int col = n0 + wn + nt * 8 + (lane & 3) * 2;
            float2 v0 = make_float2(acc[mt][nt][0], acc[mt][nt][1]);
            float2 v1 = make_float2(acc[mt][nt][2], acc[mt][nt][3]);
            *reinterpret_cast<float2*>(C + (size_t)r0 * N + col)       = v0;
            *reinterpret_cast<float2*>(C + (size_t)(r0 + 8) * N + col) = v1;
        }
    }
}

// ---------------------------------------------------------------------------
// Masked causal softmax, in-place on scores[b,t,:].
// ---------------------------------------------------------------------------
__global__ void softmax_kernel(float* __restrict__ scores,
                               const int* __restrict__ mask)
{
    const int t = blockIdx.x;
    const int b = blockIdx.y;
    float* row = scores + ((size_t)b * TT + t) * TT;
    const int* mrow = mask + b * TT;
    const int tid = threadIdx.x;

    __shared__ float red[256];

    float mx = -INFINITY;
    for (int s = tid; s <= t; s += 256)
        if (mrow[s]) mx = fmaxf(mx, row[s]);
    red[tid] = mx;
    __syncthreads();
    for (int w = 128; w > 0; w >>= 1) {
        if (tid < w) red[tid] = fmaxf(red[tid], red[tid + w]);
        __syncthreads();
    }
    mx = red[0];
    __syncthreads();

    float sum = 0.f;
    for (int s = tid; s < TT; s += 256) {
        float val = 0.f;
        if (s <= t && mrow[s]) {
            val = expf(row[s] - mx);
            sum += val;
        }
        row[s] = val;
    }
    red[tid] = sum;
    __syncthreads();
    for (int w = 128; w > 0; w >>= 1) {
        if (tid < w) red[tid] += red[tid + w];
        __syncthreads();
    }
    sum = red[0];
    __syncthreads();

    const float inv = (sum > 0.f) ? 1.f / sum : 0.f;
    for (int s = tid; s <= t; s += 256) row[s] *= inv;
}

// ---------------------------------------------------------------------------
// Launch
// ---------------------------------------------------------------------------
extern "C" void kernel_launch(void* const* d_in, const int* in_sizes, int n_in,
                              void* d_out, int out_size)
{
    const float* h    = (const float*)d_in[0];
    const float* e    = (const float*)d_in[1];
    const int*   mask = (const int*)  d_in[2];
    const float* Wq   = (const float*)d_in[3];
    const float* Wk   = (const float*)d_in[4];
    const float* Wv   = (const float*)d_in[5];
    const float* Wout = (const float*)d_in[6];
    const float* bout = (const float*)d_in[7];
    float* out = (float*)d_out;

    float *q, *k, *v, *ctx, *sc;
    cudaGetSymbolAddress((void**)&q,   g_q);
    cudaGetSymbolAddress((void**)&k,   g_k);
    cudaGetSymbolAddress((void**)&v,   g_v);
    cudaGetSymbolAddress((void**)&ctx, g_ctx);
    cudaGetSymbolAddress((void**)&sc,  g_scores);

    cudaFuncSetAttribute(tc_nt_kernel<false, false>,
                         cudaFuncAttributeMaxDynamicSharedMemorySize, GEMM_SMEM);
    cudaFuncSetAttribute(tc_nt_kernel<true, false>,
                         cudaFuncAttributeMaxDynamicSharedMemorySize, GEMM_SMEM);
    cudaFuncSetAttribute(tc_nt_kernel<false, true>,
                         cudaFuncAttributeMaxDynamicSharedMemorySize, GEMM_SMEM);
    cudaFuncSetAttribute(tc_nn_kernel,
                         cudaFuncAttributeMaxDynamicSharedMemorySize, GEMM_SMEM);

    const float att_scale = 1.0f / 32.0f;   // KV^-0.5

    // 1) QKV projections: [4096,2048] @ [1024,2048]^T
    {
        dim3 grid(MTOT / 128, KVD / 128, 1);
        tc_nt_kernel<false, false><<<grid, 256, GEMM_SMEM>>>(
            h, Wq, q, nullptr, MTOT, KVD, HID, 1.f, 0, 0, 0);
        tc_nt_kernel<false, false><<<grid, 256, GEMM_SMEM>>>(
            e, Wk, k, nullptr, MTOT, KVD, HID, 1.f, 0, 0, 0);
        tc_nt_kernel<false, false><<<grid, 256, GEMM_SMEM>>>(
            e, Wv, v, nullptr, MTOT, KVD, HID, 1.f, 0, 0, 0);
    }

    // 2) scores = scale * q @ k^T (causal block-skip), per batch
    {
        dim3 grid(TT / 128, TT / 128, BBATCH);
        tc_nt_kernel<true, false><<<grid, 256, GEMM_SMEM>>>(
            q, k, sc, nullptr, TT, TT, KVD, att_scale,
            (size_t)TT * KVD, (size_t)TT * KVD, (size_t)TT * TT);
    }

    // 3) masked causal softmax (in place; writes full rows)
    {
        dim3 grid(TT, BBATCH);
        softmax_kernel<<<grid, 256>>>(sc, mask);
    }

    // 4) ctx = attn @ V (NN, K-loop clamped by causality)
    {
        dim3 grid(TT / 128, KVD / 128, BBATCH);
        tc_nn_kernel<<<grid, 256, GEMM_SMEM>>>(
            sc, v, ctx, TT, KVD, TT,
            (size_t)TT * TT, (size_t)TT * KVD, (size_t)TT * KVD, 1);
    }

    // 5) out = ctx @ Wout^T + bout : [4096,1024] @ [32000,1024]^T
    //    x = m-blocks fastest -> consecutive CTAs share the same Wout tile,
    //    ctx (16MB) stays L2-resident.
    {
        dim3 grid(MTOT / 128, VOC / 128, 1);
        tc_nt_kernel<false, true><<<grid, 256, GEMM_SMEM>>>(
            ctx, Wout, out, bout, MTOT, VOC, KVD, 1.f, 0, 0, 0);
    }
}

// round 4
// speedup vs baseline: 2.9471x; 1.1602x over previous
#include <cuda_runtime.h>
#include <cstddef>
#include <cstdint>
#include <math.h>

// ---------------------------------------------------------------------------
// Problem dims
// ---------------------------------------------------------------------------
#define BBATCH 2
#define TT   2048
#define HID  2048
#define KVD  1024
#define VOC  32000
#define MTOT (BBATCH * TT)   // 4096

// ---------------------------------------------------------------------------
// Scratch (__device__ globals; no allocation allowed)
// All "p" buffers hold tf32-rounded bits in k-pair-permuted order:
//   pi(k) = (k & ~7) + ((k & 3) << 1) + ((k >> 2) & 1)
// ---------------------------------------------------------------------------
__device__ __align__(256) float g_hp [(size_t)MTOT * HID];
__device__ __align__(256) float g_ep [(size_t)MTOT * HID];
__device__ __align__(256) float g_wqp[(size_t)KVD * HID];
__device__ __align__(256) float g_wkp[(size_t)KVD * HID];
__device__ __align__(256) float g_wvp[(size_t)KVD * HID];
__device__ __align__(256) float g_wop[(size_t)VOC * KVD];
__device__ __align__(256) float g_q  [(size_t)MTOT * KVD];
__device__ __align__(256) float g_k  [(size_t)MTOT * KVD];
__device__ __align__(256) float g_vT [(size_t)KVD * MTOT];      // [KVD, B*T]
__device__ __align__(256) float g_ctx[(size_t)MTOT * KVD];
__device__ __align__(256) float g_scores[(size_t)BBATCH * TT * TT];

// ---------------------------------------------------------------------------
// Helpers
// ---------------------------------------------------------------------------
__device__ __forceinline__ uint32_t s2u(const void* p) {
    uint32_t a;
    asm("{ .reg .u64 t; cvta.to.shared.u64 t, %1; cvt.u32.u64 %0, t; }"
        : "=r"(a) : "l"(p));
    return a;
}

__device__ __forceinline__ void cpasync16(uint32_t dst, const void* src) {
    asm volatile("cp.async.cg.shared.global [%0], [%1], 16;"
                 :: "r"(dst), "l"(src));
}
#define CP_COMMIT() asm volatile("cp.async.commit_group;" ::: "memory")
#define CP_WAIT1()  asm volatile("cp.async.wait_group 1;"  ::: "memory")

__device__ __forceinline__ float tf32r(float f) {
    uint32_t u;
    asm("cvt.rna.tf32.f32 %0, %1;" : "=r"(u) : "f"(f));
    return __uint_as_float(u);
}

__device__ __forceinline__ void mma8(float* c, const uint32_t* a, const uint32_t* b) {
    asm volatile(
        "mma.sync.aligned.m16n8k8.row.col.f32.tf32.tf32.f32 "
        "{%0,%1,%2,%3}, {%4,%5,%6,%7}, {%8,%9}, {%0,%1,%2,%3};"
        : "+f"(c[0]), "+f"(c[1]), "+f"(c[2]), "+f"(c[3])
        : "r"(a[0]), "r"(a[1]), "r"(a[2]), "r"(a[3]),
          "r"(b[0]), "r"(b[1]));
}

// ---------------------------------------------------------------------------
// tf32 NT GEMM on pre-permuted operands.
// C[M,N] = scale * A[M,K] @ B[N,K]^T (+ bias)
// CTA 128x128, BK=32, 3-stage cp.async, 8 warps of 32x64.
// SMEM layout: element (row, pk) at float idx row*32 + (pk ^ ((row&3)*8));
// fragment (k, k+4) pair is adjacent (permuted gmem) -> one LDS.64 each.
// ---------------------------------------------------------------------------
#define STAGE_B   32768u
#define STAGE_F   8192
#define GEMM_SMEM (3 * 32768)

template <bool CAUSAL, bool HASBIAS, bool PERMOUT>
__global__ void __launch_bounds__(256, 2)
tc_nt_kernel(const float* __restrict__ A, const float* __restrict__ B,
             float* __restrict__ C, const float* __restrict__ bias,
             int M, int N, int K, int lda, int ldb, int ldc, float scale,
             size_t sA, size_t sB, size_t sC, int kClamp)
{
    extern __shared__ float sm[];
    A += (size_t)blockIdx.z * sA;
    B += (size_t)blockIdx.z * sB;
    C += (size_t)blockIdx.z * sC;
    const int m0 = blockIdx.x * 128;
    const int n0 = blockIdx.y * 128;
    if (CAUSAL && n0 > m0 + 127) return;

    const int tid  = threadIdx.x;
    const int lane = tid & 31;
    const int wid  = tid >> 5;
    const int wm   = (wid & 3) * 32;
    const int wn   = (wid >> 2) * 64;
    const uint32_t su = s2u(sm);

    // loaders: thread owns 4x16B of one A row and one B row per stage
    const int lrow = tid >> 1;
    const int kb   = (tid & 1) * 16;
    const float* Ag = A + (size_t)(m0 + lrow) * lda + kb;
    const float* Bg = B + (size_t)(n0 + lrow) * ldb + kb;
    uint32_t aoff[4], boff[4];
#pragma unroll
    for (int i = 0; i < 4; i++) {
        int kf = kb + i * 4;
        uint32_t o = (uint32_t)(lrow * 32 + (kf ^ ((lrow & 3) * 8))) * 4;
        aoff[i] = o;
        boff[i] = o + 16384u;
    }

    const int kEnd = kClamp ? (m0 + 128 < K ? m0 + 128 : K) : K;
    const int nk = kEnd / 32;

#pragma unroll
    for (int st = 0; st < 2; st++) {
#pragma unroll
        for (int i = 0; i < 4; i++) {
            cpasync16(su + (uint32_t)st * STAGE_B + aoff[i], Ag + st * 32 + i * 4);
            cpasync16(su + (uint32_t)st * STAGE_B + boff[i], Bg + st * 32 + i * 4);
        }
        CP_COMMIT();
    }

    float acc[2][8][4];
#pragma unroll
    for (int mt = 0; mt < 2; mt++)
#pragma unroll
        for (int nt = 0; nt < 8; nt++)
#pragma unroll
            for (int j = 0; j < 4; j++) acc[mt][nt][j] = 0.f;

    for (int c = 0; c < nk; c++) {
        CP_WAIT1();
        __syncthreads();

        const int p = c + 2;
        if (p < nk) {
            const uint32_t sb = (uint32_t)(p % 3) * STAGE_B;
#pragma unroll
            for (int i = 0; i < 4; i++) {
                cpasync16(su + sb + aoff[i], Ag + p * 32 + i * 4);
                cpasync16(su + sb + boff[i], Bg + p * 32 + i * 4);
            }
        }
        CP_COMMIT();

        const float* sA_ = sm + (c % 3) * STAGE_F;
        const float* sB_ = sA_ + 4096;

#pragma unroll
        for (int ks = 0; ks < 4; ks++) {
            const int kk = ks * 8 + (lane & 3) * 2;   // permuted pair base
            uint32_t bf[8][2];
#pragma unroll
            for (int nt = 0; nt < 8; nt++) {
                const int n = wn + nt * 8 + (lane >> 2);
                const uint2 bv = *reinterpret_cast<const uint2*>(
                    sB_ + n * 32 + (kk ^ ((n & 3) * 8)));
                bf[nt][0] = bv.x;
                bf[nt][1] = bv.y;
            }
#pragma unroll
            for (int mt = 0; mt < 2; mt++) {
                const int m = wm + mt * 16 + (lane >> 2);
                const int sw = (m & 3) * 8;           // (m+8)&3 == m&3
                const uint2 a02 = *reinterpret_cast<const uint2*>(
                    sA_ + m * 32 + (kk ^ sw));
                const uint2 a13 = *reinterpret_cast<const uint2*>(
                    sA_ + (m + 8) * 32 + (kk ^ sw));
                uint32_t af[4] = {a02.x, a13.x, a02.y, a13.y};
#pragma unroll
                for (int nt = 0; nt < 8; nt++)
                    mma8(acc[mt][nt], af, bf[nt]);
            }
        }
    }

    // Epilogue
#pragma unroll
    for (int mt = 0; mt < 2; mt++) {
        const int r0 = m0 + wm + mt * 16 + (lane >> 2);
#pragma unroll
        for (int nt = 0; nt < 8; nt++) {
            const int col = n0 + wn + nt * 8 + (lane & 3) * 2;
            if (PERMOUT) {
                // pi(col): col&7 = (lane&3)*2; pi0 = ((col&3)<<1) + ((col>>2)&1)
                const int c2  = (lane & 3) * 2;
                const int pc  = (col & ~7) + ((c2 & 3) * 2) + (c2 >> 2);
                float* R0 = C + (size_t)r0 * ldc + pc;
                float* R1 = C + (size_t)(r0 + 8) * ldc + pc;
                R0[0] = tf32r(acc[mt][nt][0] * scale);
                R0[2] = tf32r(acc[mt][nt][1] * scale);
                R1[0] = tf32r(acc[mt][nt][2] * scale);
                R1[2] = tf32r(acc[mt][nt][3] * scale);
            } else {
                float bx = 0.f, by = 0.f;
                if (HASBIAS) {
                    float2 bv = *reinterpret_cast<const float2*>(bias + col);
                    bx = bv.x; by = bv.y;
                }
                float2 v0 = make_float2(acc[mt][nt][0] * scale + bx,
                                        acc[mt][nt][1] * scale + by);
                float2 v1 = make_float2(acc[mt][nt][2] * scale + bx,
                                        acc[mt][nt][3] * scale + by);
                *reinterpret_cast<float2*>(C + (size_t)r0 * ldc + col)       = v0;
                *reinterpret_cast<float2*>(C + (size_t)(r0 + 8) * ldc + col) = v1;
            }
        }
    }
}

// ---------------------------------------------------------------------------
// Pack: tf32-round + k-pair permute. One float4 (8-group half) per thread.
// quad at c (c%4==0): targets base=(c&~7) + ((c>>2)&1) + {0,2,4,6}
// ---------------------------------------------------------------------------
__global__ void pack_kernel(const float* __restrict__ in, float* __restrict__ out,
                            size_t n4, int ld)
{
    size_t i = (size_t)blockIdx.x * blockDim.x + threadIdx.x;
    if (i >= n4) return;
    const size_t el = i * 4;
    const int c = (int)(el % ld);
    const size_t r = el / ld;
    const float4 q = *reinterpret_cast<const float4*>(in + el);
    float* ob = out + r * (size_t)ld + (c & ~7) + ((c >> 2) & 1);
    ob[0] = tf32r(q.x);
    ob[2] = tf32r(q.y);
    ob[4] = tf32r(q.z);
    ob[6] = tf32r(q.w);
}

// ---------------------------------------------------------------------------
// Masked causal softmax; final pass writes tf32-rounded, pi-permuted in place.
// ---------------------------------------------------------------------------
__global__ void softmax_kernel(float* __restrict__ scores,
                               const int* __restrict__ mask)
{
    const int t = blockIdx.x;
    const int b = blockIdx.y;
    float* row = scores + ((size_t)b * TT + t) * TT;
    const int* mrow = mask + b * TT;
    const int tid = threadIdx.x;

    __shared__ float red[256];

    float mx = -INFINITY;
    for (int s = tid; s <= t; s += 256)
        if (mrow[s]) mx = fmaxf(mx, row[s]);
    red[tid] = mx;
    __syncthreads();
    for (int w = 128; w > 0; w >>= 1) {
        if (tid < w) red[tid] = fmaxf(red[tid], red[tid + w]);
        __syncthreads();
    }
    mx = red[0];
    __syncthreads();

    float sum = 0.f;
    for (int s = tid; s < TT; s += 256) {
        float val = 0.f;
        if (s <= t && mrow[s]) {
            val = expf(row[s] - mx);
            sum += val;
        }
        row[s] = val;
    }
    red[tid] = sum;
    __syncthreads();
    for (int w = 128; w > 0; w >>= 1) {
        if (tid < w) red[tid] += red[tid + w];
        __syncthreads();
    }
    sum = red[0];
    __syncthreads();

    const float inv = (sum > 0.f) ? 1.f / sum : 0.f;
    // normalize + tf32 round + permute (pi stays within the warp's 32-block)
    for (int s = tid; s < TT; s += 256) {
        const float x = row[s];
        __syncwarp();
        const int ps = (s & ~7) + ((s & 3) * 2) + ((s >> 2) & 1);
        row[ps] = tf32r(x * inv);
        __syncwarp();
    }
}

// ---------------------------------------------------------------------------
// Launch
// ---------------------------------------------------------------------------
static inline int cdiv_sz(size_t a, int b) { return (int)((a + b - 1) / b); }

extern "C" void kernel_launch(void* const* d_in, const int* in_sizes, int n_in,
                              void* d_out, int out_size)
{
    const float* h    = (const float*)d_in[0];
    const float* e    = (const float*)d_in[1];
    const int*   mask = (const int*)  d_in[2];
    const float* Wq   = (const float*)d_in[3];
    const float* Wk   = (const float*)d_in[4];
    const float* Wv   = (const float*)d_in[5];
    const float* Wout = (const float*)d_in[6];
    const float* bout = (const float*)d_in[7];
    float* out = (float*)d_out;

    float *hp, *ep, *wqp, *wkp, *wvp, *wop, *q, *k, *vT, *ctx, *sc;
    cudaGetSymbolAddress((void**)&hp,  g_hp);
    cudaGetSymbolAddress((void**)&ep,  g_ep);
    cudaGetSymbolAddress((void**)&wqp, g_wqp);
    cudaGetSymbolAddress((void**)&wkp, g_wkp);
    cudaGetSymbolAddress((void**)&wvp, g_wvp);
    cudaGetSymbolAddress((void**)&wop, g_wop);
    cudaGetSymbolAddress((void**)&q,   g_q);
    cudaGetSymbolAddress((void**)&k,   g_k);
    cudaGetSymbolAddress((void**)&vT,  g_vT);
    cudaGetSymbolAddress((void**)&ctx, g_ctx);
    cudaGetSymbolAddress((void**)&sc,  g_scores);

    cudaFuncSetAttribute(tc_nt_kernel<false, false, true>,
                         cudaFuncAttributeMaxDynamicSharedMemorySize, GEMM_SMEM);
    cudaFuncSetAttribute(tc_nt_kernel<true, false, false>,
                         cudaFuncAttributeMaxDynamicSharedMemorySize, GEMM_SMEM);
    cudaFuncSetAttribute(tc_nt_kernel<false, true, false>,
                         cudaFuncAttributeMaxDynamicSharedMemorySize, GEMM_SMEM);

    const float att_scale = 1.0f / 32.0f;   // KV^-0.5
    const int PT = 256;

    // 0) pack inputs + weights (tf32 + permute)
    pack_kernel<<<cdiv_sz((size_t)MTOT*HID/4, PT), PT>>>(h,    hp,  (size_t)MTOT*HID/4, HID);
    pack_kernel<<<cdiv_sz((size_t)MTOT*HID/4, PT), PT>>>(e,    ep,  (size_t)MTOT*HID/4, HID);
    pack_kernel<<<cdiv_sz((size_t)KVD*HID/4,  PT), PT>>>(Wq,   wqp, (size_t)KVD*HID/4,  HID);
    pack_kernel<<<cdiv_sz((size_t)KVD*HID/4,  PT), PT>>>(Wk,   wkp, (size_t)KVD*HID/4,  HID);
    pack_kernel<<<cdiv_sz((size_t)KVD*HID/4,  PT), PT>>>(Wv,   wvp, (size_t)KVD*HID/4,  HID);
    pack_kernel<<<cdiv_sz((size_t)VOC*KVD/4,  PT), PT>>>(Wout, wop, (size_t)VOC*KVD/4,  KVD);

    // 1) q = h @ Wq^T, k = e @ Wk^T  (PERMOUT for downstream use)
    {
        dim3 grid(MTOT / 128, KVD / 128, 1);
        tc_nt_kernel<false, false, true><<<grid, 256, GEMM_SMEM>>>(
            hp, wqp, q, nullptr, MTOT, KVD, HID, HID, HID, KVD, 1.f, 0, 0, 0, 0);
        tc_nt_kernel<false, false, true><<<grid, 256, GEMM_SMEM>>>(
            ep, wkp, k, nullptr, MTOT, KVD, HID, HID, HID, KVD, 1.f, 0, 0, 0, 0);
    }

    // 1b) vT = Wv @ e^T : [KVD, MTOT]  (PERMOUT along the s dimension)
    {
        dim3 grid(KVD / 128, MTOT / 128, 1);
        tc_nt_kernel<false, false, true><<<grid, 256, GEMM_SMEM>>>(
            wvp, ep, vT, nullptr, KVD, MTOT, HID, HID, HID, MTOT, 1.f, 0, 0, 0, 0);
    }

    // 2) scores = scale * q @ k^T (causal block-skip), per batch, plain fp32 out
    {
        dim3 grid(TT / 128, TT / 128, BBATCH);
        tc_nt_kernel<true, false, false><<<grid, 256, GEMM_SMEM>>>(
            q, k, sc, nullptr, TT, TT, KVD, KVD, KVD, TT, att_scale,
            (size_t)TT * KVD, (size_t)TT * KVD, (size_t)TT * TT, 0);
    }

    // 3) softmax (in place; emits tf32 + permuted attn)
    {
        dim3 grid(TT, BBATCH);
        softmax_kernel<<<grid, 256>>>(sc, mask);
    }

    // 4) ctx = attn @ V = NT(attn, vT), K clamped by causality; PERMOUT
    {
        dim3 grid(TT / 128, KVD / 128, BBATCH);
        tc_nt_kernel<false, false, true><<<grid, 256, GEMM_SMEM>>>(
            sc, vT, ctx, nullptr, TT, KVD, TT, TT, MTOT, KVD, 1.f,
            (size_t)TT * TT, (size_t)TT /* vT col offset per batch */,
            (size_t)TT * KVD, 1);
    }

    // 5) out = ctx @ Wout^T + bout
    {
        dim3 grid(MTOT / 128, VOC / 128, 1);
        tc_nt_kernel<false, true, false><<<grid, 256, GEMM_SMEM>>>(
            ctx, wop, out, bout, MTOT, VOC, KVD, KVD, KVD, VOC, 1.f, 0, 0, 0, 0);
    }
}

// round 5
// speedup vs baseline: 3.1070x; 1.0543x over previous
#include <cuda_runtime.h>
#include <cstddef>
#include <cstdint>
#include <math.h>

// ---------------------------------------------------------------------------
// Problem dims
// ---------------------------------------------------------------------------
#define BBATCH 2
#define TT   2048
#define HID  2048
#define KVD  1024
#define VOC  32000
#define MTOT (BBATCH * TT)   // 4096

// ---------------------------------------------------------------------------
// Scratch (__device__ globals).  "p" buffers hold tf32-rounded bits in
// k-pair-permuted order: pi(k) = (k & ~7) + ((k & 3) << 1) + ((k >> 2) & 1)
// ---------------------------------------------------------------------------
__device__ __align__(256) float g_hp [(size_t)MTOT * HID];
__device__ __align__(256) float g_ep [(size_t)MTOT * HID];
__device__ __align__(256) float g_wqp[(size_t)KVD * HID];
__device__ __align__(256) float g_wkp[(size_t)KVD * HID];
__device__ __align__(256) float g_wvp[(size_t)KVD * HID];
__device__ __align__(256) float g_wop[(size_t)VOC * KVD];
__device__ __align__(256) float g_q  [(size_t)MTOT * KVD];
__device__ __align__(256) float g_k  [(size_t)MTOT * KVD];
__device__ __align__(256) float g_vT [(size_t)KVD * MTOT];      // [KVD, B*T]
__device__ __align__(256) float g_ctx[(size_t)MTOT * KVD];
__device__ __align__(256) float g_scores[(size_t)BBATCH * TT * TT];

// ---------------------------------------------------------------------------
// Helpers
// ---------------------------------------------------------------------------
__device__ __forceinline__ uint32_t s2u(const void* p) {
    uint32_t a;
    asm("{ .reg .u64 t; cvta.to.shared.u64 t, %1; cvt.u32.u64 %0, t; }"
        : "=r"(a) : "l"(p));
    return a;
}

__device__ __forceinline__ void cpasync16(uint32_t dst, const void* src) {
    asm volatile("cp.async.cg.shared.global [%0], [%1], 16;"
                 :: "r"(dst), "l"(src));
}
#define CP_COMMIT() asm volatile("cp.async.commit_group;" ::: "memory")
#define CP_WAIT1()  asm volatile("cp.async.wait_group 1;"  ::: "memory")

__device__ __forceinline__ float tf32r(float f) {
    uint32_t u;
    asm("cvt.rna.tf32.f32 %0, %1;" : "=r"(u) : "f"(f));
    return __uint_as_float(u);
}

__device__ __forceinline__ void mma8(float* c, const uint32_t* a, const uint32_t* b) {
    asm volatile(
        "mma.sync.aligned.m16n8k8.row.col.f32.tf32.tf32.f32 "
        "{%0,%1,%2,%3}, {%4,%5,%6,%7}, {%8,%9}, {%0,%1,%2,%3};"
        : "+f"(c[0]), "+f"(c[1]), "+f"(c[2]), "+f"(c[3])
        : "r"(a[0]), "r"(a[1]), "r"(a[2]), "r"(a[3]),
          "r"(b[0]), "r"(b[1]));
}

// ---------------------------------------------------------------------------
// tf32 NT GEMM on pre-permuted operands.
// C[M,N] = scale * A[M,K] @ B[N,K]^T (+ bias)
// CTA 128(M) x 256(N), BK=32, 3-stage cp.async, 8 warps of 64x64.
// SMEM element (row, pk) at float idx row*32 + (pk ^ ((row&3)*8)).
// Fragments double-buffered across ks-steps.
// ---------------------------------------------------------------------------
#define BM 128
#define BN 256
#define STAGE_F   ((BM + BN) * 32)          // 12288 floats
#define STAGE_B   (STAGE_F * 4u)            // 49152 bytes
#define B_OFF_F   (BM * 32)                 // 4096 floats
#define GEMM_SMEM (3 * (int)STAGE_B)        // 147456

template <bool CAUSAL, bool HASBIAS, bool PERMOUT>
__global__ void __launch_bounds__(256, 1)
tc_nt_kernel(const float* __restrict__ A, const float* __restrict__ B,
             float* __restrict__ C, const float* __restrict__ bias,
             int M, int N, int K, int lda, int ldb, int ldc, float scale,
             size_t sA, size_t sB, size_t sC, int kClamp)
{
    extern __shared__ float sm[];
    A += (size_t)blockIdx.z * sA;
    B += (size_t)blockIdx.z * sB;
    C += (size_t)blockIdx.z * sC;
    const int m0 = blockIdx.x * BM;
    const int n0 = blockIdx.y * BN;
    if (CAUSAL && n0 > m0 + (BM - 1)) return;

    const int tid  = threadIdx.x;
    const int lane = tid & 31;
    const int wid  = tid >> 5;
    const int wm   = (wid & 1) * 64;        // 2 m-halves
    const int wn   = (wid >> 1) * 64;       // 4 n-quarters
    const uint32_t su = s2u(sm);

    // loaders: A rows 0..127 (2 thr/row, 4 chunks), B rows r and r+128 (8 chunks)
    const int lrow = tid >> 1;
    const int kb   = (tid & 1) * 16;
    const float* Ag  = A + (size_t)(m0 + lrow) * lda + kb;
    const float* Bg0 = B + (size_t)(n0 + lrow) * ldb + kb;
    const float* Bg1 = Bg0 + (size_t)128 * ldb;
    uint32_t aoff[4], boff[4];
#pragma unroll
    for (int i = 0; i < 4; i++) {
        int kf = kb + i * 4;
        uint32_t o = (uint32_t)(lrow * 32 + (kf ^ ((lrow & 3) * 8))) * 4;
        aoff[i] = o;
        boff[i] = o + B_OFF_F * 4u;         // B region; rows r and r+128 share swizzle
    }

    const int kEnd = kClamp ? (m0 + BM < K ? m0 + BM : K) : K;
    const int nk = kEnd / 32;

#pragma unroll
    for (int st = 0; st < 2; st++) {
        const uint32_t sb = su + (uint32_t)st * STAGE_B;
#pragma unroll
        for (int i = 0; i < 4; i++) {
            cpasync16(sb + aoff[i], Ag + st * 32 + i * 4);
            cpasync16(sb + boff[i], Bg0 + st * 32 + i * 4);
            cpasync16(sb + boff[i] + 128u * 32u * 4u, Bg1 + st * 32 + i * 4);
        }
        CP_COMMIT();
    }

    float acc[4][8][4];
#pragma unroll
    for (int mt = 0; mt < 4; mt++)
#pragma unroll
        for (int nt = 0; nt < 8; nt++)
#pragma unroll
            for (int j = 0; j < 4; j++) acc[mt][nt][j] = 0.f;

    const int lg = lane >> 2;               // group row/col
    uint32_t af[2][4][4], bf[2][8][2];

    for (int c = 0; c < nk; c++) {
        CP_WAIT1();
        __syncthreads();

        const int p = c + 2;
        if (p < nk) {
            const uint32_t sb = su + (uint32_t)(p % 3) * STAGE_B;
#pragma unroll
            for (int i = 0; i < 4; i++) {
                cpasync16(sb + aoff[i], Ag + p * 32 + i * 4);
                cpasync16(sb + boff[i], Bg0 + p * 32 + i * 4);
                cpasync16(sb + boff[i] + 128u * 32u * 4u, Bg1 + p * 32 + i * 4);
            }
        }
        CP_COMMIT();

        const float* sA_ = sm + (c % 3) * STAGE_F;
        const float* sB_ = sA_ + B_OFF_F;

        // load ks=0 fragments
        {
            const int kk = (lane & 3) * 2;
#pragma unroll
            for (int nt = 0; nt < 8; nt++) {
                const int n = wn + nt * 8 + lg;
                const uint2 bv = *reinterpret_cast<const uint2*>(
                    sB_ + n * 32 + (kk ^ ((n & 3) * 8)));
                bf[0][nt][0] = bv.x; bf[0][nt][1] = bv.y;
            }
#pragma unroll
            for (int mt = 0; mt < 4; mt++) {
                const int m = wm + mt * 16 + lg;
                const int sw = (m & 3) * 8;
                const uint2 a02 = *reinterpret_cast<const uint2*>(
                    sA_ + m * 32 + (kk ^ sw));
                const uint2 a13 = *reinterpret_cast<const uint2*>(
                    sA_ + (m + 8) * 32 + (kk ^ sw));
                af[0][mt][0] = a02.x; af[0][mt][1] = a13.x;
                af[0][mt][2] = a02.y; af[0][mt][3] = a13.y;
            }
        }

#pragma unroll
        for (int ks = 0; ks < 4; ks++) {
            const int cur = ks & 1, nxt = cur ^ 1;
            if (ks < 3) {   // prefetch next ks fragments
                const int kk = (ks + 1) * 8 + (lane & 3) * 2;
#pragma unroll
                for (int nt = 0; nt < 8; nt++) {
                    const int n = wn + nt * 8 + lg;
                    const uint2 bv = *reinterpret_cast<const uint2*>(
                        sB_ + n * 32 + (kk ^ ((n & 3) * 8)));
                    bf[nxt][nt][0] = bv.x; bf[nxt][nt][1] = bv.y;
                }
#pragma unroll
                for (int mt = 0; mt < 4; mt++) {
                    const int m = wm + mt * 16 + lg;
                    const int sw = (m & 3) * 8;
                    const uint2 a02 = *reinterpret_cast<const uint2*>(
                        sA_ + m * 32 + (kk ^ sw));
                    const uint2 a13 = *reinterpret_cast<const uint2*>(
                        sA_ + (m + 8) * 32 + (kk ^ sw));
                    af[nxt][mt][0] = a02.x; af[nxt][mt][1] = a13.x;
                    af[nxt][mt][2] = a02.y; af[nxt][mt][3] = a13.y;
                }
            }
#pragma unroll
            for (int mt = 0; mt < 4; mt++)
#pragma unroll
                for (int nt = 0; nt < 8; nt++)
                    mma8(acc[mt][nt], af[cur][mt], bf[cur][nt]);
        }
    }

    // Epilogue
#pragma unroll
    for (int mt = 0; mt < 4; mt++) {
        const int r0 = m0 + wm + mt * 16 + lg;
#pragma unroll
        for (int nt = 0; nt < 8; nt++) {
            const int col = n0 + wn + nt * 8 + (lane & 3) * 2;
            if (PERMOUT) {
                const int c2 = (lane & 3) * 2;
                const int pc = (col & ~7) + ((c2 & 3) * 2) + (c2 >> 2);
                float* R0 = C + (size_t)r0 * ldc + pc;
                float* R1 = C + (size_t)(r0 + 8) * ldc + pc;
                R0[0] = tf32r(acc[mt][nt][0] * scale);
                R0[2] = tf32r(acc[mt][nt][1] * scale);
                R1[0] = tf32r(acc[mt][nt][2] * scale);
                R1[2] = tf32r(acc[mt][nt][3] * scale);
            } else {
                float bx = 0.f, by = 0.f;
                if (HASBIAS) {
                    float2 bv = *reinterpret_cast<const float2*>(bias + col);
                    bx = bv.x; by = bv.y;
                }
                float2 v0 = make_float2(acc[mt][nt][0] * scale + bx,
                                        acc[mt][nt][1] * scale + by);
                float2 v1 = make_float2(acc[mt][nt][2] * scale + bx,
                                        acc[mt][nt][3] * scale + by);
                *reinterpret_cast<float2*>(C + (size_t)r0 * ldc + col)       = v0;
                *reinterpret_cast<float2*>(C + (size_t)(r0 + 8) * ldc + col) = v1;
            }
        }
    }
}

// ---------------------------------------------------------------------------
// Pack: tf32-round + k-pair permute (float4 per thread).
// ---------------------------------------------------------------------------
__global__ void pack_kernel(const float* __restrict__ in, float* __restrict__ out,
                            size_t n4, int ld)
{
    size_t i = (size_t)blockIdx.x * blockDim.x + threadIdx.x;
    if (i >= n4) return;
    const size_t el = i * 4;
    const int c = (int)(el % ld);
    const size_t r = el / ld;
    const float4 q = *reinterpret_cast<const float4*>(in + el);
    float* ob = out + r * (size_t)ld + (c & ~7) + ((c >> 2) & 1);
    ob[0] = tf32r(q.x);
    ob[2] = tf32r(q.y);
    ob[4] = tf32r(q.z);
    ob[6] = tf32r(q.w);
}

// ---------------------------------------------------------------------------
// Masked causal softmax; final pass writes tf32-rounded, pi-permuted in place.
// ---------------------------------------------------------------------------
__global__ void softmax_kernel(float* __restrict__ scores,
                               const int* __restrict__ mask)
{
    const int t = blockIdx.x;
    const int b = blockIdx.y;
    float* row = scores + ((size_t)b * TT + t) * TT;
    const int* mrow = mask + b * TT;
    const int tid = threadIdx.x;

    __shared__ float red[256];

    float mx = -INFINITY;
    for (int s = tid; s <= t; s += 256)
        if (mrow[s]) mx = fmaxf(mx, row[s]);
    red[tid] = mx;
    __syncthreads();
    for (int w = 128; w > 0; w >>= 1) {
        if (tid < w) red[tid] = fmaxf(red[tid], red[tid + w]);
        __syncthreads();
    }
    mx = red[0];
    __syncthreads();

    float sum = 0.f;
    for (int s = tid; s < TT; s += 256) {
        float val = 0.f;
        if (s <= t && mrow[s]) {
            val = expf(row[s] - mx);
            sum += val;
        }
        row[s] = val;
    }
    red[tid] = sum;
    __syncthreads();
    for (int w = 128; w > 0; w >>= 1) {
        if (tid < w) red[tid] += red[tid + w];
        __syncthreads();
    }
    sum = red[0];
    __syncthreads();

    const float inv = (sum > 0.f) ? 1.f / sum : 0.f;
    for (int s = tid; s < TT; s += 256) {
        const float x = row[s];
        __syncwarp();
        const int ps = (s & ~7) + ((s & 3) * 2) + ((s >> 2) & 1);
        row[ps] = tf32r(x * inv);
        __syncwarp();
    }
}

// ---------------------------------------------------------------------------
// Launch
// ---------------------------------------------------------------------------
static inline int cdiv_sz(size_t a, int b) { return (int)((a + b - 1) / b); }

extern "C" void kernel_launch(void* const* d_in, const int* in_sizes, int n_in,
                              void* d_out, int out_size)
{
    const float* h    = (const float*)d_in[0];
    const float* e    = (const float*)d_in[1];
    const int*   mask = (const int*)  d_in[2];
    const float* Wq   = (const float*)d_in[3];
    const float* Wk   = (const float*)d_in[4];
    const float* Wv   = (const float*)d_in[5];
    const float* Wout = (const float*)d_in[6];
    const float* bout = (const float*)d_in[7];
    float* out = (float*)d_out;

    float *hp, *ep, *wqp, *wkp, *wvp, *wop, *q, *k, *vT, *ctx, *sc;
    cudaGetSymbolAddress((void**)&hp,  g_hp);
    cudaGetSymbolAddress((void**)&ep,  g_ep);
    cudaGetSymbolAddress((void**)&wqp, g_wqp);
    cudaGetSymbolAddress((void**)&wkp, g_wkp);
    cudaGetSymbolAddress((void**)&wvp, g_wvp);
    cudaGetSymbolAddress((void**)&wop, g_wop);
    cudaGetSymbolAddress((void**)&q,   g_q);
    cudaGetSymbolAddress((void**)&k,   g_k);
    cudaGetSymbolAddress((void**)&vT,  g_vT);
    cudaGetSymbolAddress((void**)&ctx, g_ctx);
    cudaGetSymbolAddress((void**)&sc,  g_scores);

    cudaFuncSetAttribute(tc_nt_kernel<false, false, true>,
                         cudaFuncAttributeMaxDynamicSharedMemorySize, GEMM_SMEM);
    cudaFuncSetAttribute(tc_nt_kernel<true, false, false>,
                         cudaFuncAttributeMaxDynamicSharedMemorySize, GEMM_SMEM);
    cudaFuncSetAttribute(tc_nt_kernel<false, true, false>,
                         cudaFuncAttributeMaxDynamicSharedMemorySize, GEMM_SMEM);

    const float att_scale = 1.0f / 32.0f;   // KV^-0.5
    const int PT = 256;

    // 0) pack inputs + weights (tf32 + permute)
    pack_kernel<<<cdiv_sz((size_t)MTOT*HID/4, PT), PT>>>(h,    hp,  (size_t)MTOT*HID/4, HID);
    pack_kernel<<<cdiv_sz((size_t)MTOT*HID/4, PT), PT>>>(e,    ep,  (size_t)MTOT*HID/4, HID);
    pack_kernel<<<cdiv_sz((size_t)KVD*HID/4,  PT), PT>>>(Wq,   wqp, (size_t)KVD*HID/4,  HID);
    pack_kernel<<<cdiv_sz((size_t)KVD*HID/4,  PT), PT>>>(Wk,   wkp, (size_t)KVD*HID/4,  HID);
    pack_kernel<<<cdiv_sz((size_t)KVD*HID/4,  PT), PT>>>(Wv,   wvp, (size_t)KVD*HID/4,  HID);
    pack_kernel<<<cdiv_sz((size_t)VOC*KVD/4,  PT), PT>>>(Wout, wop, (size_t)VOC*KVD/4,  KVD);

    // 1) q = h @ Wq^T, k = e @ Wk^T  (PERMOUT for downstream use)
    {
        dim3 grid(MTOT / BM, KVD / BN, 1);
        tc_nt_kernel<false, false, true><<<grid, 256, GEMM_SMEM>>>(
            hp, wqp, q, nullptr, MTOT, KVD, HID, HID, HID, KVD, 1.f, 0, 0, 0, 0);
        tc_nt_kernel<false, false, true><<<grid, 256, GEMM_SMEM>>>(
            ep, wkp, k, nullptr, MTOT, KVD, HID, HID, HID, KVD, 1.f, 0, 0, 0, 0);
    }

    // 1b) vT = Wv @ e^T : [KVD, MTOT]  (PERMOUT along the s dimension)
    {
        dim3 grid(KVD / BM, MTOT / BN, 1);
        tc_nt_kernel<false, false, true><<<grid, 256, GEMM_SMEM>>>(
            wvp, ep, vT, nullptr, KVD, MTOT, HID, HID, HID, MTOT, 1.f, 0, 0, 0, 0);
    }

    // 2) scores = scale * q @ k^T (causal block-skip), per batch, plain fp32 out
    {
        dim3 grid(TT / BM, TT / BN, BBATCH);
        tc_nt_kernel<true, false, false><<<grid, 256, GEMM_SMEM>>>(
            q, k, sc, nullptr, TT, TT, KVD, KVD, KVD, TT, att_scale,
            (size_t)TT * KVD, (size_t)TT * KVD, (size_t)TT * TT, 0);
    }

    // 3) softmax (in place; emits tf32 + permuted attn)
    {
        dim3 grid(TT, BBATCH);
        softmax_kernel<<<grid, 256>>>(sc, mask);
    }

    // 4) ctx = attn @ V = NT(attn, vT), K clamped by causality; PERMOUT
    {
        dim3 grid(TT / BM, KVD / BN, BBATCH);
        tc_nt_kernel<false, false, true><<<grid, 256, GEMM_SMEM>>>(
            sc, vT, ctx, nullptr, TT, KVD, TT, TT, MTOT, KVD, 1.f,
            (size_t)TT * TT, (size_t)TT, (size_t)TT * KVD, 1);
    }

    // 5) out = ctx @ Wout^T + bout  (m-fast grid: ctx stays L2-resident)
    {
        dim3 grid(MTOT / BM, VOC / BN, 1);
        tc_nt_kernel<false, true, false><<<grid, 256, GEMM_SMEM>>>(
            ctx, wop, out, bout, MTOT, VOC, KVD, KVD, KVD, VOC, 1.f, 0, 0, 0, 0);
    }
}

// round 6
// speedup vs baseline: 6.7126x; 2.1605x over previous
#include <cuda_runtime.h>
#include <cuda_fp16.h>
#include <cstddef>
#include <cstdint>
#include <math.h>

// ---------------------------------------------------------------------------
// Problem dims
// ---------------------------------------------------------------------------
#define BBATCH 2
#define TT   2048
#define HID  2048
#define KVD  1024
#define VOC  32000
#define MTOT (BBATCH * TT)   // 4096

// ---------------------------------------------------------------------------
// Scratch. fp16 buffers hold k-permuted data: within each 16-group, order is
// [0,1,8,9, 2,3,10,11, 4,5,12,13, 6,7,14,15]  (quad [k,k+1,k+8,k+9] adjacent)
// slot(e) = (e&1) + (((e>>1)&3)<<2) + (((e>>3)&1)<<1)
// ---------------------------------------------------------------------------
__device__ __align__(256) __half g_hp [(size_t)MTOT * HID];
__device__ __align__(256) __half g_ep [(size_t)MTOT * HID];
__device__ __align__(256) __half g_wqp[(size_t)KVD * HID];
__device__ __align__(256) __half g_wkp[(size_t)KVD * HID];
__device__ __align__(256) __half g_wvp[(size_t)KVD * HID];
__device__ __align__(256) __half g_wop[(size_t)VOC * KVD];
__device__ __align__(256) __half g_q  [(size_t)MTOT * KVD];
__device__ __align__(256) __half g_k  [(size_t)MTOT * KVD];
__device__ __align__(256) __half g_vT [(size_t)KVD * MTOT];     // [KVD, B*T]
__device__ __align__(256) __half g_ctx[(size_t)MTOT * KVD];
__device__ __align__(256) __half g_attn[(size_t)MTOT * TT];
__device__ __align__(256) float  g_scores[(size_t)BBATCH * TT * TT];

// ---------------------------------------------------------------------------
// Helpers
// ---------------------------------------------------------------------------
__device__ __forceinline__ uint32_t s2u(const void* p) {
    uint32_t a;
    asm("{ .reg .u64 t; cvta.to.shared.u64 t, %1; cvt.u32.u64 %0, t; }"
        : "=r"(a) : "l"(p));
    return a;
}

__device__ __forceinline__ void cpasync16(uint32_t dst, const void* src) {
    asm volatile("cp.async.cg.shared.global [%0], [%1], 16;"
                 :: "r"(dst), "l"(src));
}
#define CP_COMMIT() asm volatile("cp.async.commit_group;" ::: "memory")
#define CP_WAIT1()  asm volatile("cp.async.wait_group 1;"  ::: "memory")

__device__ __forceinline__ void mma16(float* c, const uint32_t* a, const uint32_t* b) {
    asm volatile(
        "mma.sync.aligned.m16n8k16.row.col.f32.f16.f16.f32 "
        "{%0,%1,%2,%3}, {%4,%5,%6,%7}, {%8,%9}, {%0,%1,%2,%3};"
        : "+f"(c[0]), "+f"(c[1]), "+f"(c[2]), "+f"(c[3])
        : "r"(a[0]), "r"(a[1]), "r"(a[2]), "r"(a[3]),
          "r"(b[0]), "r"(b[1]));
}

// permuted slot for even local index e (0..15)
__device__ __forceinline__ int slot_even(int e) {
    return (((e >> 1) & 3) << 2) + (((e >> 3) & 1) << 1);
}

// ---------------------------------------------------------------------------
// fp16 NT GEMM on pre-permuted operands.
// C[M,N] = scale * A[M,K] @ B[N,K]^T (+ bias)
// CTA 128(M) x 256(N), BK=32 halves, 3-stage cp.async, 8 warps of 64x64.
// SMEM: row = 64B (32 halves); swizzle: byte ^= ((row>>1)&1)*32.
// ---------------------------------------------------------------------------
#define BM 128
#define BN 256
#define STAGE_BYTES 24576u                 // (128+256) * 64B
#define B_OFF_BYTES 8192u                  // A = 128*64
#define GEMM_SMEM   (3 * 24576)            // 73728

template <bool CAUSAL, bool HASBIAS, bool PERMOUT>
__global__ void __launch_bounds__(256, 1)
tc_nt_kernel(const __half* __restrict__ A, const __half* __restrict__ B,
             void* __restrict__ Cv, const float* __restrict__ bias,
             int M, int N, int K, int lda, int ldb, int ldc, float scale,
             size_t sA, size_t sB, size_t sC, int kClamp)
{
    extern __shared__ __align__(16) char smc[];
    A += (size_t)blockIdx.z * sA;
    B += (size_t)blockIdx.z * sB;
    const int m0 = blockIdx.x * BM;
    const int n0 = blockIdx.y * BN;
    if (CAUSAL && n0 > m0 + (BM - 1)) return;

    const int tid  = threadIdx.x;
    const int lane = tid & 31;
    const int wid  = tid >> 5;
    const int wm   = (wid & 1) * 64;
    const int wn   = (wid >> 1) * 64;
    const uint32_t su = s2u(smc);

    // loaders: thread t -> rows (t>>2)+i*64, 16B chunk (t&3)
    const int arow = tid >> 2;
    const uint32_t co = (uint32_t)((tid & 3) * 16);
    const uint32_t off0 = (uint32_t)arow * 64u + (co ^ ((((uint32_t)arow >> 1) & 1u) << 5));
    const __half* Ag0 = A + (size_t)(m0 + arow) * lda + (tid & 3) * 8;
    const __half* Ag1 = Ag0 + (size_t)64 * lda;
    const __half* Bg0 = B + (size_t)(n0 + arow) * ldb + (tid & 3) * 8;
    const __half* Bg1 = Bg0 + (size_t)64 * ldb;
    const __half* Bg2 = Bg0 + (size_t)128 * ldb;
    const __half* Bg3 = Bg0 + (size_t)192 * ldb;

    const int kEnd = kClamp ? (m0 + BM < K ? m0 + BM : K) : K;
    const int nk = kEnd / 32;

#pragma unroll
    for (int st = 0; st < 2; st++) {
        const uint32_t sb = su + (uint32_t)st * STAGE_BYTES;
        const int kh = st * 32;
        cpasync16(sb + off0,                 Ag0 + kh);
        cpasync16(sb + off0 + 4096u,         Ag1 + kh);
        cpasync16(sb + B_OFF_BYTES + off0,           Bg0 + kh);
        cpasync16(sb + B_OFF_BYTES + off0 + 4096u,   Bg1 + kh);
        cpasync16(sb + B_OFF_BYTES + off0 + 8192u,   Bg2 + kh);
        cpasync16(sb + B_OFF_BYTES + off0 + 12288u,  Bg3 + kh);
        CP_COMMIT();
    }

    float acc[4][8][4];
#pragma unroll
    for (int mt = 0; mt < 4; mt++)
#pragma unroll
        for (int nt = 0; nt < 8; nt++)
#pragma unroll
            for (int j = 0; j < 4; j++) acc[mt][nt][j] = 0.f;

    const int lg = lane >> 2;
    const int lq = (lane & 3) * 4;          // quad offset in halves
    uint32_t af[2][4][4], bf[2][8][2];

    for (int c = 0; c < nk; c++) {
        CP_WAIT1();
        __syncthreads();

        const int p = c + 2;
        if (p < nk) {
            const uint32_t sb = su + (uint32_t)(p % 3) * STAGE_BYTES;
            const int kh = p * 32;
            cpasync16(sb + off0,                 Ag0 + kh);
            cpasync16(sb + off0 + 4096u,         Ag1 + kh);
            cpasync16(sb + B_OFF_BYTES + off0,           Bg0 + kh);
            cpasync16(sb + B_OFF_BYTES + off0 + 4096u,   Bg1 + kh);
            cpasync16(sb + B_OFF_BYTES + off0 + 8192u,   Bg2 + kh);
            cpasync16(sb + B_OFF_BYTES + off0 + 12288u,  Bg3 + kh);
        }
        CP_COMMIT();

        const __half* sA_ = (const __half*)(smc + (c % 3) * STAGE_BYTES);
        const __half* sB_ = sA_ + 4096;     // 8192 bytes

        // fragment load for ks (k-half-group within BK=32)
#pragma unroll
        for (int pre = 0; pre < 1; pre++) { // load ks=0 into buf 0
            const int kh = lq;              // ks=0
#pragma unroll
            for (int nt = 0; nt < 8; nt++) {
                const int n = wn + nt * 8 + lg;
                const uint2 bv = *reinterpret_cast<const uint2*>(
                    sB_ + n * 32 + (kh ^ (((n >> 1) & 1) << 4)));
                bf[0][nt][0] = bv.x; bf[0][nt][1] = bv.y;
            }
#pragma unroll
            for (int mt = 0; mt < 4; mt++) {
                const int m = wm + mt * 16 + lg;
                const int sw = ((m >> 1) & 1) << 4;
                const uint2 lm  = *reinterpret_cast<const uint2*>(
                    sA_ + m * 32 + (kh ^ sw));
                const uint2 lm8 = *reinterpret_cast<const uint2*>(
                    sA_ + (m + 8) * 32 + (kh ^ sw));
                af[0][mt][0] = lm.x;  af[0][mt][1] = lm8.x;
                af[0][mt][2] = lm.y;  af[0][mt][3] = lm8.y;
            }
        }

#pragma unroll
        for (int ks = 0; ks < 2; ks++) {
            const int cur = ks & 1, nxt = cur ^ 1;
            if (ks < 1) {                   // prefetch ks=1 fragments
                const int kh = 16 + lq;
#pragma unroll
                for (int nt = 0; nt < 8; nt++) {
                    const int n = wn + nt * 8 + lg;
                    const uint2 bv = *reinterpret_cast<const uint2*>(
                        sB_ + n * 32 + (kh ^ (((n >> 1) & 1) << 4)));
                    bf[nxt][nt][0] = bv.x; bf[nxt][nt][1] = bv.y;
                }
#pragma unroll
                for (int mt = 0; mt < 4; mt++) {
                    const int m = wm + mt * 16 + lg;
                    const int sw = ((m >> 1) & 1) << 4;
                    const uint2 lm  = *reinterpret_cast<const uint2*>(
                        sA_ + m * 32 + (kh ^ sw));
                    const uint2 lm8 = *reinterpret_cast<const uint2*>(
                        sA_ + (m + 8) * 32 + (kh ^ sw));
                    af[nxt][mt][0] = lm.x;  af[nxt][mt][1] = lm8.x;
                    af[nxt][mt][2] = lm.y;  af[nxt][mt][3] = lm8.y;
                }
            }
#pragma unroll
            for (int mt = 0; mt < 4; mt++)
#pragma unroll
                for (int nt = 0; nt < 8; nt++)
                    mma16(acc[mt][nt], af[cur][mt], bf[cur][nt]);
        }
    }

    // Epilogue
    if (PERMOUT) {
        __half* Ch = (__half*)Cv + (size_t)blockIdx.z * sC;
#pragma unroll
        for (int mt = 0; mt < 4; mt++) {
            const int r0 = m0 + wm + mt * 16 + lg;
#pragma unroll
            for (int nt = 0; nt < 8; nt++) {
                const int col = n0 + wn + nt * 8 + (lane & 3) * 2;
                const int pc = (col & ~15) + slot_even(col & 15);
                __half2 v0 = __floats2half2_rn(acc[mt][nt][0] * scale,
                                               acc[mt][nt][1] * scale);
                __half2 v1 = __floats2half2_rn(acc[mt][nt][2] * scale,
                                               acc[mt][nt][3] * scale);
                *reinterpret_cast<__half2*>(Ch + (size_t)r0 * ldc + pc)       = v0;
                *reinterpret_cast<__half2*>(Ch + (size_t)(r0 + 8) * ldc + pc) = v1;
            }
        }
    } else {
        float* Cf = (float*)Cv + (size_t)blockIdx.z * sC;
#pragma unroll
        for (int mt = 0; mt < 4; mt++) {
            const int r0 = m0 + wm + mt * 16 + lg;
#pragma unroll
            for (int nt = 0; nt < 8; nt++) {
                const int col = n0 + wn + nt * 8 + (lane & 3) * 2;
                float bx = 0.f, by = 0.f;
                if (HASBIAS) {
                    float2 bv = *reinterpret_cast<const float2*>(bias + col);
                    bx = bv.x; by = bv.y;
                }
                float2 v0 = make_float2(acc[mt][nt][0] * scale + bx,
                                        acc[mt][nt][1] * scale + by);
                float2 v1 = make_float2(acc[mt][nt][2] * scale + bx,
                                        acc[mt][nt][3] * scale + by);
                *reinterpret_cast<float2*>(Cf + (size_t)r0 * ldc + col)       = v0;
                *reinterpret_cast<float2*>(Cf + (size_t)(r0 + 8) * ldc + col) = v1;
            }
        }
    }
}

// ---------------------------------------------------------------------------
// Pack: fp32 -> fp16 with k-permutation (float4 per thread).
// ---------------------------------------------------------------------------
__global__ void pack_kernel(const float* __restrict__ in, __half* __restrict__ out,
                            size_t n4, int ld)
{
    size_t i = (size_t)blockIdx.x * blockDim.x + threadIdx.x;
    if (i >= n4) return;
    const size_t el = i * 4;
    const int c = (int)(el % ld);
    const size_t r = el / ld;
    const float4 q = *reinterpret_cast<const float4*>(in + el);
    __half* ob = out + r * (size_t)ld + (c & ~15);
    const int e = c & 15;
    *reinterpret_cast<__half2*>(ob + slot_even(e))     = __floats2half2_rn(q.x, q.y);
    *reinterpret_cast<__half2*>(ob + slot_even(e + 2)) = __floats2half2_rn(q.z, q.w);
}

// ---------------------------------------------------------------------------
// Masked causal softmax: reads fp32 scores, writes fp16 permuted attn.
// ---------------------------------------------------------------------------
__global__ void softmax_kernel(float* __restrict__ scores,
                               __half* __restrict__ attn,
                               const int* __restrict__ mask)
{
    const int t = blockIdx.x;
    const int b = blockIdx.y;
    float* row = scores + ((size_t)b * TT + t) * TT;
    __half* arow = attn + ((size_t)b * TT + t) * TT;
    const int* mrow = mask + b * TT;
    const int tid = threadIdx.x;

    __shared__ float red[256];

    float mx = -INFINITY;
    for (int s = tid; s <= t; s += 256)
        if (mrow[s]) mx = fmaxf(mx, row[s]);
    red[tid] = mx;
    __syncthreads();
    for (int w = 128; w > 0; w >>= 1) {
        if (tid < w) red[tid] = fmaxf(red[tid], red[tid + w]);
        __syncthreads();
    }
    mx = red[0];
    __syncthreads();

    float sum = 0.f;
    for (int s = tid; s < TT; s += 256) {
        float val = 0.f;
        if (s <= t && mrow[s]) {
            val = expf(row[s] - mx);
            sum += val;
        }
        row[s] = val;
    }
    red[tid] = sum;
    __syncthreads();
    for (int w = 128; w > 0; w >>= 1) {
        if (tid < w) red[tid] += red[tid + w];
        __syncthreads();
    }
    sum = red[0];
    __syncthreads();

    const float inv = (sum > 0.f) ? 1.f / sum : 0.f;
    for (int s = tid; s < TT; s += 256) {
        const int e = s & 15;
        const int ps = (s & ~15) + (e & 1) + (((e >> 1) & 3) << 2) + (((e >> 3) & 1) << 1);
        arow[ps] = __float2half(row[s] * inv);
    }
}

// ---------------------------------------------------------------------------
// Launch
// ---------------------------------------------------------------------------
static inline int cdiv_sz(size_t a, int b) { return (int)((a + b - 1) / b); }

extern "C" void kernel_launch(void* const* d_in, const int* in_sizes, int n_in,
                              void* d_out, int out_size)
{
    const float* h    = (const float*)d_in[0];
    const float* e    = (const float*)d_in[1];
    const int*   mask = (const int*)  d_in[2];
    const float* Wq   = (const float*)d_in[3];
    const float* Wk   = (const float*)d_in[4];
    const float* Wv   = (const float*)d_in[5];
    const float* Wout = (const float*)d_in[6];
    const float* bout = (const float*)d_in[7];
    float* out = (float*)d_out;

    __half *hp, *ep, *wqp, *wkp, *wvp, *wop, *q, *k, *vT, *ctx, *attn;
    float *sc;
    cudaGetSymbolAddress((void**)&hp,   g_hp);
    cudaGetSymbolAddress((void**)&ep,   g_ep);
    cudaGetSymbolAddress((void**)&wqp,  g_wqp);
    cudaGetSymbolAddress((void**)&wkp,  g_wkp);
    cudaGetSymbolAddress((void**)&wvp,  g_wvp);
    cudaGetSymbolAddress((void**)&wop,  g_wop);
    cudaGetSymbolAddress((void**)&q,    g_q);
    cudaGetSymbolAddress((void**)&k,    g_k);
    cudaGetSymbolAddress((void**)&vT,   g_vT);
    cudaGetSymbolAddress((void**)&ctx,  g_ctx);
    cudaGetSymbolAddress((void**)&attn, g_attn);
    cudaGetSymbolAddress((void**)&sc,   g_scores);

    cudaFuncSetAttribute(tc_nt_kernel<false, false, true>,
                         cudaFuncAttributeMaxDynamicSharedMemorySize, GEMM_SMEM);
    cudaFuncSetAttribute(tc_nt_kernel<true, false, false>,
                         cudaFuncAttributeMaxDynamicSharedMemorySize, GEMM_SMEM);
    cudaFuncSetAttribute(tc_nt_kernel<false, true, false>,
                         cudaFuncAttributeMaxDynamicSharedMemorySize, GEMM_SMEM);

    const float att_scale = 1.0f / 32.0f;   // KV^-0.5
    const int PT = 256;

    // 0) pack inputs + weights (fp16 + permute)
    pack_kernel<<<cdiv_sz((size_t)MTOT*HID/4, PT), PT>>>(h,    hp,  (size_t)MTOT*HID/4, HID);
    pack_kernel<<<cdiv_sz((size_t)MTOT*HID/4, PT), PT>>>(e,    ep,  (size_t)MTOT*HID/4, HID);
    pack_kernel<<<cdiv_sz((size_t)KVD*HID/4,  PT), PT>>>(Wq,   wqp, (size_t)KVD*HID/4,  HID);
    pack_kernel<<<cdiv_sz((size_t)KVD*HID/4,  PT), PT>>>(Wk,   wkp, (size_t)KVD*HID/4,  HID);
    pack_kernel<<<cdiv_sz((size_t)KVD*HID/4,  PT), PT>>>(Wv,   wvp, (size_t)KVD*HID/4,  HID);
    pack_kernel<<<cdiv_sz((size_t)VOC*KVD/4,  PT), PT>>>(Wout, wop, (size_t)VOC*KVD/4,  KVD);

    // 1) q = h @ Wq^T, k = e @ Wk^T  (fp16-permuted outputs)
    {
        dim3 grid(MTOT / BM, KVD / BN, 1);
        tc_nt_kernel<false, false, true><<<grid, 256, GEMM_SMEM>>>(
            hp, wqp, q, nullptr, MTOT, KVD, HID, HID, HID, KVD, 1.f, 0, 0, 0, 0);
        tc_nt_kernel<false, false, true><<<grid, 256, GEMM_SMEM>>>(
            ep, wkp, k, nullptr, MTOT, KVD, HID, HID, HID, KVD, 1.f, 0, 0, 0, 0);
    }

    // 1b) vT = Wv @ e^T : [KVD, MTOT]
    {
        dim3 grid(KVD / BM, MTOT / BN, 1);
        tc_nt_kernel<false, false, true><<<grid, 256, GEMM_SMEM>>>(
            wvp, ep, vT, nullptr, KVD, MTOT, HID, HID, HID, MTOT, 1.f, 0, 0, 0, 0);
    }

    // 2) scores = scale * q @ k^T (causal block-skip), fp32 out, per batch
    {
        dim3 grid(TT / BM, TT / BN, BBATCH);
        tc_nt_kernel<true, false, false><<<grid, 256, GEMM_SMEM>>>(
            q, k, sc, nullptr, TT, TT, KVD, KVD, KVD, TT, att_scale,
            (size_t)TT * KVD, (size_t)TT * KVD, (size_t)TT * TT, 0);
    }

    // 3) softmax -> fp16 permuted attn
    {
        dim3 grid(TT, BBATCH);
        softmax_kernel<<<grid, 256>>>(sc, attn, mask);
    }

    // 4) ctx = attn @ V = NT(attn, vT), K clamped by causality
    {
        dim3 grid(TT / BM, KVD / BN, BBATCH);
        tc_nt_kernel<false, false, true><<<grid, 256, GEMM_SMEM>>>(
            attn, vT, ctx, nullptr, TT, KVD, TT, TT, MTOT, KVD, 1.f,
            (size_t)TT * TT, (size_t)TT, (size_t)TT * KVD, 1);
    }

    // 5) out = ctx @ Wout^T + bout  (m-fast grid: ctx stays L2-resident)
    {
        dim3 grid(MTOT / BM, VOC / BN, 1);
        tc_nt_kernel<false, true, false><<<grid, 256, GEMM_SMEM>>>(
            ctx, wop, out, bout, MTOT, VOC, KVD, KVD, KVD, VOC, 1.f, 0, 0, 0, 0);
    }
}